// round 11
// baseline (speedup 1.0000x reference)
#include <cuda_runtime.h>
#include <cstdint>

// IPLayer segment-sum: out[atom][g] += inter[pair][g], atom = ind_2[pair][0].
// Bulk-copy (UBLKCP) pipeline: stage inter+idx tiles into smem on the TMA/bulk
// engine (off the LSU/L1tex pipe), consume from smem, scatter with red.v4.f32.

#define N_INTER 64
#define TILE 128
#define INTER_TILE_BYTES (TILE * N_INTER * 4)        // 32768
#define IDX_TILE_BYTES   (TILE * 8)                  // 1024
#define OFF_INTER0 0
#define OFF_IDX0   (INTER_TILE_BYTES)                // 32768
#define OFF_INTER1 (OFF_IDX0 + IDX_TILE_BYTES)       // 33792
#define OFF_IDX1   (OFF_INTER1 + INTER_TILE_BYTES)   // 66560
#define OFF_MBAR   (OFF_IDX1 + IDX_TILE_BYTES)       // 67584
#define SMEM_TOTAL (OFF_MBAR + 16)
#define TX_BYTES (INTER_TILE_BYTES + IDX_TILE_BYTES)

__global__ void zero_out_kernel(float4* __restrict__ out, int n4) {
    int i = blockIdx.x * blockDim.x + threadIdx.x;
    if (i < n4) out[i] = make_float4(0.f, 0.f, 0.f, 0.f);
}

__device__ __forceinline__ uint32_t s2u(const void* p) {
    uint32_t a;
    asm("{ .reg .u64 t; cvta.to.shared.u64 t, %1; cvt.u32.u64 %0, t; }"
        : "=r"(a) : "l"(p));
    return a;
}
__device__ __forceinline__ void mbar_init(uint32_t m, int cnt) {
    asm volatile("mbarrier.init.shared::cta.b64 [%0], %1;" :: "r"(m), "r"(cnt) : "memory");
}
__device__ __forceinline__ void mbar_expect(uint32_t m, uint32_t tx) {
    asm volatile("mbarrier.arrive.expect_tx.shared::cta.b64 _, [%0], %1;"
                 :: "r"(m), "r"(tx) : "memory");
}
__device__ __forceinline__ void bulk_g2s(uint32_t dst, const void* src,
                                         uint32_t bytes, uint32_t mbar) {
    asm volatile("cp.async.bulk.shared::cta.global.mbarrier::complete_tx::bytes "
                 "[%0], [%1], %2, [%3];"
                 :: "r"(dst), "l"(src), "r"(bytes), "r"(mbar) : "memory");
}
__device__ __forceinline__ void mbar_wait(uint32_t m, uint32_t parity) {
    asm volatile(
        "{\n\t.reg .pred P;\n\t"
        "WL_%=:\n\t"
        "mbarrier.try_wait.parity.acquire.cta.shared::cta.b64 P, [%0], %1, 0x989680;\n\t"
        "@P bra.uni WD_%=;\n\t"
        "bra.uni WL_%=;\n\t"
        "WD_%=:\n\t}"
        :: "r"(m), "r"(parity) : "memory");
}

// 256 threads = 8 warps. Warp w owns pairs [w*16, w*16+16) of the tile.
// lane = h*16 + c: c = float4 chunk, h = which 8-pair half. Every red.v4
// warp instruction covers two dense 256B rows (unchanged from champion).
__global__ void __launch_bounds__(256) seg_red_pipe(
        const char* __restrict__ inter_bytes,
        const char* __restrict__ idx_bytes,
        float* __restrict__ out,
        int n_tiles) {
    extern __shared__ char smem[];
    uint32_t sb = s2u(smem);
    int tid = threadIdx.x;
    uint32_t mb0 = sb + OFF_MBAR, mb1 = sb + OFF_MBAR + 8;

    if (tid == 0) {
        mbar_init(mb0, 1);
        mbar_init(mb1, 1);
        asm volatile("fence.proxy.async.shared::cta;" ::: "memory");
    }
    __syncthreads();

    long long t0 = blockIdx.x;
    long long stride = gridDim.x;

    // Prologue: fill both stages.
    if (tid == 0) {
        for (int k = 0; k < 2; k++) {
            long long t = t0 + (long long)k * stride;
            if (t < n_tiles) {
                uint32_t mbk = k ? mb1 : mb0;
                mbar_expect(mbk, TX_BYTES);
                bulk_g2s(sb + (k ? OFF_INTER1 : OFF_INTER0),
                         inter_bytes + t * (long long)INTER_TILE_BYTES,
                         INTER_TILE_BYTES, mbk);
                bulk_g2s(sb + (k ? OFF_IDX1 : OFF_IDX0),
                         idx_bytes + t * (long long)IDX_TILE_BYTES,
                         IDX_TILE_BYTES, mbk);
            }
        }
    }

    int w = tid >> 5, lane = tid & 31;
    int c = lane & 15, h = lane >> 4;
    int pb = w * 16 + h * 8;

    uint32_t phase0 = 0, phase1 = 0;
    int it = 0;
    for (long long t = t0; t < n_tiles; t += stride, it++) {
        int s = it & 1;
        uint32_t mbs = s ? mb1 : mb0;
        mbar_wait(mbs, s ? phase1 : phase0);
        if (s) phase1 ^= 1; else phase0 ^= 1;

        const int2*   sidx = (const int2*)(smem + (s ? OFF_IDX1 : OFF_IDX0));
        const float4* sint = (const float4*)(smem + (s ? OFF_INTER1 : OFF_INTER0));

        int a[8];
#pragma unroll
        for (int j = 0; j < 8; j++) a[j] = sidx[pb + j].x;
#pragma unroll
        for (int j = 0; j < 8; j++) {
            float4 v = sint[(pb + j) * 16 + c];
            float* dst = out + (size_t)a[j] * N_INTER + c * 4;
            asm volatile("red.global.add.v4.f32 [%0], {%1,%2,%3,%4};"
                         :: "l"(dst), "f"(v.x), "f"(v.y), "f"(v.z), "f"(v.w)
                         : "memory");
        }
        __syncthreads();   // all lanes done reading stage s

        long long tn = t + 2 * stride;
        if (tid == 0 && tn < n_tiles) {
            mbar_expect(mbs, TX_BYTES);
            bulk_g2s(sb + (s ? OFF_INTER1 : OFF_INTER0),
                     inter_bytes + tn * (long long)INTER_TILE_BYTES,
                     INTER_TILE_BYTES, mbs);
            bulk_g2s(sb + (s ? OFF_IDX1 : OFF_IDX0),
                     idx_bytes + tn * (long long)IDX_TILE_BYTES,
                     IDX_TILE_BYTES, mbs);
        }
    }
}

// Tail pairs (n_pairs % TILE): direct path, 16 lanes per pair.
__global__ void seg_red_tail(const int* __restrict__ ind2,
                             const float4* __restrict__ inter,
                             float* __restrict__ out,
                             int p_start, int n_pairs) {
    int i = blockIdx.x * blockDim.x + threadIdx.x;
    int p = p_start + (i >> 4);
    int c = i & 15;
    if (p >= n_pairs) return;
    int a = __ldg(&ind2[2 * p]);
    float4 v = inter[(size_t)p * 16 + c];
    float* dst = out + (size_t)a * N_INTER + c * 4;
    asm volatile("red.global.add.v4.f32 [%0], {%1,%2,%3,%4};"
                 :: "l"(dst), "f"(v.x), "f"(v.y), "f"(v.z), "f"(v.w) : "memory");
}

extern "C" void kernel_launch(void* const* d_in, const int* in_sizes, int n_in,
                              void* d_out, int out_size) {
    const int*    ind2  = (const int*)d_in[0];
    const float4* inter = (const float4*)d_in[2];
    float*        out   = (float*)d_out;

    int n_pairs = in_sizes[0] / 2;

    int n4 = out_size / 4;
    zero_out_kernel<<<(n4 + 255) / 256, 256>>>((float4*)out, n4);

    int n_tiles = n_pairs / TILE;
    if (n_tiles > 0) {
        cudaFuncSetAttribute(seg_red_pipe,
                             cudaFuncAttributeMaxDynamicSharedMemorySize, SMEM_TOTAL);
        int grid = 148 * 3;               // 3 CTAs/SM at ~67.6KB smem each
        if (grid > n_tiles) grid = n_tiles;
        seg_red_pipe<<<grid, 256, SMEM_TOTAL>>>((const char*)inter,
                                                (const char*)ind2, out, n_tiles);
    }

    int p_start = n_tiles * TILE;
    int tail = n_pairs - p_start;
    if (tail > 0) {
        int tw = tail * 16;
        seg_red_tail<<<(tw + 255) / 256, 256>>>(ind2, inter, out, p_start, n_pairs);
    }
}

// round 12
// speedup vs baseline: 1.1298x; 1.1298x over previous
#include <cuda_runtime.h>
#include <cstdint>

// IPLayer segment-sum: out[atom][g] += inter[pair][g] for atom = ind_2[pair][0]
// Inputs (metadata order): ind_2 (int32, N_PAIRS*2), prop (float32, N_ATOMS*128),
//                          inter (float32, N_PAIRS*64). Output: float32 N_ATOMS*64.
//
// Converged design: dense-sector red.global.add.v4.f32 scatter (16 lanes/row,
// 4 pairs/thread, streaming ldcs loads). Kernel runs at ~97% of the LTS
// aggregate-throughput floor (~1.66GB through L2 at the ~6300 B/cyc cap);
// remaining optimization is host-side overhead: zeroing via a memset node
// instead of a kernel launch.

#define N_INTER 64
#define PP      4   // pairs per thread

// 16 lanes cover one pair's 256B row (one float4 chunk per lane, dense sectors).
// Each thread handles PP consecutive pairs for the SAME chunk c: independent
// index + row loads issued up front (MLP>=4), then PP red.global.add.v4.f32.
__global__ void seg_red_kernel(const int* __restrict__ ind2,
                               const float4* __restrict__ inter,
                               float* __restrict__ out,
                               int n_pairs) {
    int i = blockIdx.x * blockDim.x + threadIdx.x;
    int g = i >> 4;          // pair-group index (PP pairs)
    int c = i & 15;          // float4 chunk within the 64-float row
    int p0 = g * PP;
    if (p0 >= n_pairs) return;

    if (p0 + PP <= n_pairs) {
        // Streaming (evict-first) index loads.
        int a0 = __ldcs(&ind2[2 * (p0 + 0)]);
        int a1 = __ldcs(&ind2[2 * (p0 + 1)]);
        int a2 = __ldcs(&ind2[2 * (p0 + 2)]);
        int a3 = __ldcs(&ind2[2 * (p0 + 3)]);

        // Streaming (evict-first) row loads: one-touch data, keep out of L2.
        const float4* src = inter + (size_t)p0 * (N_INTER / 4) + c;
        float4 v0 = __ldcs(src + 0 * (N_INTER / 4));
        float4 v1 = __ldcs(src + 1 * (N_INTER / 4));
        float4 v2 = __ldcs(src + 2 * (N_INTER / 4));
        float4 v3 = __ldcs(src + 3 * (N_INTER / 4));

        float* d0 = out + (size_t)a0 * N_INTER + c * 4;
        float* d1 = out + (size_t)a1 * N_INTER + c * 4;
        float* d2 = out + (size_t)a2 * N_INTER + c * 4;
        float* d3 = out + (size_t)a3 * N_INTER + c * 4;

        asm volatile("red.global.add.v4.f32 [%0], {%1,%2,%3,%4};"
                     :: "l"(d0), "f"(v0.x), "f"(v0.y), "f"(v0.z), "f"(v0.w) : "memory");
        asm volatile("red.global.add.v4.f32 [%0], {%1,%2,%3,%4};"
                     :: "l"(d1), "f"(v1.x), "f"(v1.y), "f"(v1.z), "f"(v1.w) : "memory");
        asm volatile("red.global.add.v4.f32 [%0], {%1,%2,%3,%4};"
                     :: "l"(d2), "f"(v2.x), "f"(v2.y), "f"(v2.z), "f"(v2.w) : "memory");
        asm volatile("red.global.add.v4.f32 [%0], {%1,%2,%3,%4};"
                     :: "l"(d3), "f"(v3.x), "f"(v3.y), "f"(v3.z), "f"(v3.w) : "memory");
    } else {
        // Tail: per-pair.
        for (int p = p0; p < n_pairs; p++) {
            int a = __ldcs(&ind2[2 * p]);
            float4 v = __ldcs(&inter[(size_t)p * (N_INTER / 4) + c]);
            float* dst = out + (size_t)a * N_INTER + c * 4;
            asm volatile("red.global.add.v4.f32 [%0], {%1,%2,%3,%4};"
                         :: "l"(dst), "f"(v.x), "f"(v.y), "f"(v.z), "f"(v.w) : "memory");
        }
    }
}

extern "C" void kernel_launch(void* const* d_in, const int* in_sizes, int n_in,
                              void* d_out, int out_size) {
    const int*    ind2  = (const int*)d_in[0];
    const float4* inter = (const float4*)d_in[2];
    float*        out   = (float*)d_out;

    int n_pairs = in_sizes[0] / 2;

    // Zero the (poisoned) output via a memset node (graph-capturable,
    // no alloc): float 0.0f is all-zero bytes.
    cudaMemsetAsync(out, 0, (size_t)out_size * sizeof(float));

    // Scatter-add: 16 lanes x PP pairs per thread.
    int n_groups = (n_pairs + PP - 1) / PP;
    long long n_work = (long long)n_groups * 16;
    int blocks = (int)((n_work + 255) / 256);
    seg_red_kernel<<<blocks, 256>>>(ind2, inter, out, n_pairs);
}